// round 5
// baseline (speedup 1.0000x reference)
#include <cuda_runtime.h>
#include <cuda_bf16.h>
#include <stdint.h>

// Shapes: B=2, S=4096, H=1024, M=B*S=8192
#define BDIM 2
#define SDIM 4096
#define HDIM 1024
#define MDIM 8192

// GEMM tile config
#define TM 128
#define TN 128
#define TKB 32                 // K elements (bf16) per smem stage
#define ROWB 80                // bytes per smem row (64B payload + 16B pad)
#define TILE_BYTES (128 * ROWB)        // 10240
#define SA_HI 0
#define SA_LO (TILE_BYTES)
#define SB_HI (2 * TILE_BYTES)
#define SB_LO (3 * TILE_BYTES)
#define STAGE_BYTES (4 * TILE_BYTES)   // 40960
#define DSMEM_BYTES (2 * STAGE_BYTES)  // 81920

// ---------------- scratch (device globals) ----------------
__device__ __nv_bfloat16 g_xhi[(size_t)MDIM*HDIM],  g_xlo[(size_t)MDIM*HDIM];
__device__ __nv_bfloat16 g_wqhi[(size_t)HDIM*HDIM], g_wqlo[(size_t)HDIM*HDIM];
__device__ __nv_bfloat16 g_wkhi[(size_t)HDIM*HDIM], g_wklo[(size_t)HDIM*HDIM];
__device__ __nv_bfloat16 g_wvhi[(size_t)HDIM*HDIM], g_wvlo[(size_t)HDIM*HDIM];
__device__ __nv_bfloat16 g_wohi[(size_t)HDIM*HDIM], g_wolo[(size_t)HDIM*HDIM];
__device__ __nv_bfloat16 g_qhi[(size_t)MDIM*HDIM],  g_qlo[(size_t)MDIM*HDIM];
__device__ __nv_bfloat16 g_khi[(size_t)MDIM*HDIM],  g_klo[(size_t)MDIM*HDIM];
__device__ __nv_bfloat16 g_vthi[(size_t)HDIM*MDIM], g_vtlo[(size_t)HDIM*MDIM];
__device__ __nv_bfloat16 g_athi[(size_t)MDIM*HDIM], g_atlo[(size_t)MDIM*HDIM];
__device__ __nv_bfloat16 g_phi[(size_t)BDIM*SDIM*SDIM], g_plo[(size_t)BDIM*SDIM*SDIM];
__device__ float g_s[(size_t)BDIM*SDIM*SDIM];

// ---------------- PTX helpers ----------------
__device__ __forceinline__ void cp16(void* dst, const void* src) {
    uint32_t d = (uint32_t)__cvta_generic_to_shared(dst);
    asm volatile("cp.async.cg.shared.global [%0], [%1], 16;\n" :: "r"(d), "l"(src));
}
#define CP_COMMIT() asm volatile("cp.async.commit_group;\n" ::: "memory")
#define CP_WAIT(n)  asm volatile("cp.async.wait_group %0;\n" :: "n"(n) : "memory")

__device__ __forceinline__ void mma_bf16(float* d, const uint32_t* a, const uint32_t* b) {
    asm volatile(
        "mma.sync.aligned.m16n8k16.row.col.f32.bf16.bf16.f32 "
        "{%0,%1,%2,%3}, {%4,%5,%6,%7}, {%8,%9}, {%0,%1,%2,%3};\n"
        : "+f"(d[0]), "+f"(d[1]), "+f"(d[2]), "+f"(d[3])
        : "r"(a[0]), "r"(a[1]), "r"(a[2]), "r"(a[3]), "r"(b[0]), "r"(b[1]));
}

// ---------------------------------------------------------------------------
// Stage loader: A tile (128 x 32) hi/lo, B tile (128 x 32) hi/lo -> smem.
// Row stride ROWB=80B (64B payload). 512 16B-chunks per tile, 2 per thread.
// ---------------------------------------------------------------------------
__device__ __forceinline__ void stage_loads(
    char* base, int tid,
    const __nv_bfloat16* Ah, const __nv_bfloat16* Al, long long ldA, long long m0,
    const __nv_bfloat16* Bh, const __nv_bfloat16* Bl, long long ldB, long long n0,
    long long kof)
{
    #pragma unroll
    for (int i = 0; i < 2; i++) {
        int idx = tid + i * 256;
        int r = idx >> 2, ch = idx & 3;
        int so = r * ROWB + ch * 16;
        long long goA = (m0 + r) * ldA + kof + ch * 8;
        long long goB = (n0 + r) * ldB + kof + ch * 8;
        cp16(base + SA_HI + so, Ah + goA);
        cp16(base + SA_LO + so, Al + goA);
        cp16(base + SB_HI + so, Bh + goB);
        cp16(base + SB_LO + so, Bl + goB);
    }
}

// ---------------------------------------------------------------------------
// One pass over a stage with a given (A, B) operand selection (one split term):
// 2 k-steps of m16n8k16 over warp tile 64x32.
// ---------------------------------------------------------------------------
__device__ __forceinline__ void compute_term(
    const char* at, const char* bt, int warp_m, int warp_n, int lane,
    float acc[4][4][4])
{
    const int r = lane >> 2;    // 0..7
    const int c = lane & 3;     // 0..3
    #pragma unroll
    for (int ks = 0; ks < 2; ks++) {
        const int kb = ks * 16;  // k offset (elements)
        uint32_t af[4][4], bf[4][2];
        #pragma unroll
        for (int mt = 0; mt < 4; mt++) {
            const char* rowp = at + (warp_m * 64 + mt * 16 + r) * ROWB + (kb + 2 * c) * 2;
            af[mt][0] = *reinterpret_cast<const uint32_t*>(rowp);
            af[mt][1] = *reinterpret_cast<const uint32_t*>(rowp + 8 * ROWB);
            af[mt][2] = *reinterpret_cast<const uint32_t*>(rowp + 16);
            af[mt][3] = *reinterpret_cast<const uint32_t*>(rowp + 8 * ROWB + 16);
        }
        #pragma unroll
        for (int nt = 0; nt < 4; nt++) {
            const char* colp = bt + (warp_n * 32 + nt * 8 + r) * ROWB + (kb + 2 * c) * 2;
            bf[nt][0] = *reinterpret_cast<const uint32_t*>(colp);
            bf[nt][1] = *reinterpret_cast<const uint32_t*>(colp + 16);
        }
        #pragma unroll
        for (int mt = 0; mt < 4; mt++)
            #pragma unroll
            for (int nt = 0; nt < 4; nt++)
                mma_bf16(acc[mt][nt], af[mt], bf[nt]);
    }
}

// ---------------------------------------------------------------------------
// NT GEMM, bf16 hi/lo split operands (3 terms: hh + hl + lh), fp32 accum:
//   C[m,n] = alpha * sum_k (Ahi+Alo)[m,k]*(Bhi+Blo)[n,k] + bias
// Output: fp32 (Cf) or bf16 hi/lo pair (Chi/Clo).
// bias_mode: 0 none, 1 per-column (n), 2 per-row (m).
// ---------------------------------------------------------------------------
__global__ __launch_bounds__(256, 1)
void gemm_nt_bf3(const __nv_bfloat16* __restrict__ Ah, const __nv_bfloat16* __restrict__ Al, long long ldA,
                 const __nv_bfloat16* __restrict__ Bh, const __nv_bfloat16* __restrict__ Bl, long long ldB,
                 float* __restrict__ Cf, __nv_bfloat16* __restrict__ Chi, __nv_bfloat16* __restrict__ Clo,
                 long long ldC,
                 const float* __restrict__ bias, int bias_mode, float alpha, int K,
                 long long sA, long long sB, long long sC)
{
    extern __shared__ char smem[];

    const int tid  = threadIdx.x;
    const int lane = tid & 31;
    const int wid  = tid >> 5;
    const int warp_m = wid & 1;   // 2 x 64 rows
    const int warp_n = wid >> 1;  // 4 x 32 cols

    Ah += (long long)blockIdx.z * sA;  Al += (long long)blockIdx.z * sA;
    Bh += (long long)blockIdx.z * sB;  Bl += (long long)blockIdx.z * sB;
    if (Cf)  Cf  += (long long)blockIdx.z * sC;
    if (Chi) { Chi += (long long)blockIdx.z * sC; Clo += (long long)blockIdx.z * sC; }

    const long long m0 = (long long)blockIdx.y * TM;
    const long long n0 = (long long)blockIdx.x * TN;

    float acc[4][4][4];
    #pragma unroll
    for (int i = 0; i < 4; i++)
        #pragma unroll
        for (int j = 0; j < 4; j++)
            #pragma unroll
            for (int q = 0; q < 4; q++) acc[i][j][q] = 0.f;

    const int nkt = K / TKB;

    stage_loads(smem, tid, Ah, Al, ldA, m0, Bh, Bl, ldB, n0, 0);
    CP_COMMIT();

    for (int kt = 0; kt < nkt; ++kt) {
        char* cur = smem + (kt & 1) * STAGE_BYTES;
        if (kt + 1 < nkt) {
            stage_loads(smem + ((kt + 1) & 1) * STAGE_BYTES, tid, Ah, Al, ldA, m0,
                        Bh, Bl, ldB, n0, (long long)(kt + 1) * TKB);
            CP_COMMIT();
            CP_WAIT(1);
        } else {
            CP_WAIT(0);
        }
        __syncthreads();

        // 3 split terms, one fragment set live at a time
        compute_term(cur + SA_LO, cur + SB_HI, warp_m, warp_n, lane, acc); // lo*hi
        compute_term(cur + SA_HI, cur + SB_LO, warp_m, warp_n, lane, acc); // hi*lo
        compute_term(cur + SA_HI, cur + SB_HI, warp_m, warp_n, lane, acc); // hi*hi

        __syncthreads();
    }

    // Epilogue
    const int r = lane >> 2;
    const int c = lane & 3;
    float bias_r0[4], bias_r1[4];
    if (bias_mode == 2) {
        #pragma unroll
        for (int mt = 0; mt < 4; mt++) {
            long long row = m0 + warp_m * 64 + mt * 16 + r;
            bias_r0[mt] = bias[row];
            bias_r1[mt] = bias[row + 8];
        }
    }

    #pragma unroll
    for (int mt = 0; mt < 4; mt++) {
        long long row = m0 + warp_m * 64 + mt * 16 + r;
        #pragma unroll
        for (int nt = 0; nt < 4; nt++) {
            long long col = n0 + warp_n * 32 + nt * 8 + 2 * c;
            float b0 = 0.f, b1 = 0.f, b0b = 0.f, b1b = 0.f;
            if (bias_mode == 1) {
                b0 = bias[col]; b1 = bias[col + 1]; b0b = b0; b1b = b1;
            } else if (bias_mode == 2) {
                b0 = bias_r0[mt]; b1 = b0; b0b = bias_r1[mt]; b1b = b0b;
            }
            float v00 = alpha * acc[mt][nt][0] + b0;
            float v01 = alpha * acc[mt][nt][1] + b1;
            float v10 = alpha * acc[mt][nt][2] + b0b;
            float v11 = alpha * acc[mt][nt][3] + b1b;
            if (Cf) {
                *reinterpret_cast<float2*>(Cf + row * ldC + col)       = make_float2(v00, v01);
                *reinterpret_cast<float2*>(Cf + (row + 8) * ldC + col) = make_float2(v10, v11);
            } else {
                __nv_bfloat16 h00 = __float2bfloat16(v00);
                __nv_bfloat16 h01 = __float2bfloat16(v01);
                __nv_bfloat16 h10 = __float2bfloat16(v10);
                __nv_bfloat16 h11 = __float2bfloat16(v11);
                __nv_bfloat162 hp0; hp0.x = h00; hp0.y = h01;
                __nv_bfloat162 hp1; hp1.x = h10; hp1.y = h11;
                __nv_bfloat162 lp0;
                lp0.x = __float2bfloat16(v00 - __bfloat162float(h00));
                lp0.y = __float2bfloat16(v01 - __bfloat162float(h01));
                __nv_bfloat162 lp1;
                lp1.x = __float2bfloat16(v10 - __bfloat162float(h10));
                lp1.y = __float2bfloat16(v11 - __bfloat162float(h11));
                *reinterpret_cast<__nv_bfloat162*>(Chi + row * ldC + col)       = hp0;
                *reinterpret_cast<__nv_bfloat162*>(Chi + (row + 8) * ldC + col) = hp1;
                *reinterpret_cast<__nv_bfloat162*>(Clo + row * ldC + col)       = lp0;
                *reinterpret_cast<__nv_bfloat162*>(Clo + (row + 8) * ldC + col) = lp1;
            }
        }
    }
}

// ---------------------------------------------------------------------------
// fp32 -> bf16 hi/lo split (elementwise)
// ---------------------------------------------------------------------------
__global__ void split_fp32(const float* __restrict__ src,
                           __nv_bfloat16* __restrict__ hi,
                           __nv_bfloat16* __restrict__ lo, long long n)
{
    long long i = (long long)blockIdx.x * blockDim.x + threadIdx.x;
    long long stride = (long long)gridDim.x * blockDim.x;
    for (; i < n; i += stride) {
        float v = src[i];
        __nv_bfloat16 h = __float2bfloat16(v);
        hi[i] = h;
        lo[i] = __float2bfloat16(v - __bfloat162float(h));
    }
}

// ---------------------------------------------------------------------------
// Row softmax over 4096 cols; writes bf16 hi/lo split of probabilities.
// ---------------------------------------------------------------------------
__device__ __forceinline__ float warp_max(float v) {
    #pragma unroll
    for (int o = 16; o > 0; o >>= 1) v = fmaxf(v, __shfl_xor_sync(0xffffffffu, v, o));
    return v;
}
__device__ __forceinline__ float warp_sum(float v) {
    #pragma unroll
    for (int o = 16; o > 0; o >>= 1) v += __shfl_xor_sync(0xffffffffu, v, o);
    return v;
}

__global__ __launch_bounds__(256)
void softmax_rows(const float* __restrict__ S,
                  __nv_bfloat16* __restrict__ Phi, __nv_bfloat16* __restrict__ Plo)
{
    const int tid = threadIdx.x;
    const size_t base = (size_t)blockIdx.x * SDIM;
    const float* r = S + base;

    __shared__ float red[8];

    float v[16];
    float mx = -1e30f;
    #pragma unroll
    for (int i = 0; i < 16; i++) {
        v[i] = r[tid + i * 256];
        mx = fmaxf(mx, v[i]);
    }
    mx = warp_max(mx);
    if ((tid & 31) == 0) red[tid >> 5] = mx;
    __syncthreads();
    {
        float t = (tid < 8) ? red[tid] : -1e30f;
        t = warp_max(t);
        if (tid == 0) red[0] = t;
    }
    __syncthreads();
    mx = red[0];
    __syncthreads();

    float sum = 0.f;
    #pragma unroll
    for (int i = 0; i < 16; i++) {
        v[i] = __expf(v[i] - mx);
        sum += v[i];
    }
    sum = warp_sum(sum);
    if ((tid & 31) == 0) red[tid >> 5] = sum;
    __syncthreads();
    {
        float t = (tid < 8) ? red[tid] : 0.f;
        t = warp_sum(t);
        if (tid == 0) red[0] = t;
    }
    __syncthreads();
    const float inv = 1.f / red[0];

    #pragma unroll
    for (int i = 0; i < 16; i++) {
        float p = v[i] * inv;
        __nv_bfloat16 h = __float2bfloat16(p);
        __nv_bfloat16 l = __float2bfloat16(p - __bfloat162float(h));
        Phi[base + tid + i * 256] = h;
        Plo[base + tid + i * 256] = l;
    }
}

// ---------------------------------------------------------------------------
// Launch
// ---------------------------------------------------------------------------
extern "C" void kernel_launch(void* const* d_in, const int* in_sizes, int n_in,
                              void* d_out, int out_size)
{
    const float* x  = (const float*)d_in[0];
    const float* Wq = (const float*)d_in[1];
    const float* bq = (const float*)d_in[2];
    const float* Wk = (const float*)d_in[3];
    const float* bk = (const float*)d_in[4];
    const float* Wv = (const float*)d_in[5];
    const float* bv = (const float*)d_in[6];
    const float* Wo = (const float*)d_in[7];
    const float* bo = (const float*)d_in[8];
    float* out = (float*)d_out;

    cudaFuncSetAttribute(gemm_nt_bf3, cudaFuncAttributeMaxDynamicSharedMemorySize, DSMEM_BYTES);

    const dim3 blk(256);

    // 1) split inputs to bf16 hi/lo
    split_fp32<<<1024, 256>>>(x,  g_xhi,  g_xlo,  (long long)MDIM * HDIM);
    split_fp32<<<256,  256>>>(Wq, g_wqhi, g_wqlo, (long long)HDIM * HDIM);
    split_fp32<<<256,  256>>>(Wk, g_wkhi, g_wklo, (long long)HDIM * HDIM);
    split_fp32<<<256,  256>>>(Wv, g_wvhi, g_wvlo, (long long)HDIM * HDIM);
    split_fp32<<<256,  256>>>(Wo, g_wohi, g_wolo, (long long)HDIM * HDIM);

    // 2) Q = x Wq^T + bq  -> split bf16   [8192 x 1024]
    dim3 gproj(HDIM / TN, MDIM / TM, 1);   // (8, 64)
    gemm_nt_bf3<<<gproj, blk, DSMEM_BYTES>>>(g_xhi, g_xlo, HDIM, g_wqhi, g_wqlo, HDIM,
        nullptr, g_qhi, g_qlo, HDIM, bq, 1, 1.f, HDIM, 0, 0, 0);
    // 3) K
    gemm_nt_bf3<<<gproj, blk, DSMEM_BYTES>>>(g_xhi, g_xlo, HDIM, g_wkhi, g_wklo, HDIM,
        nullptr, g_khi, g_klo, HDIM, bk, 1, 1.f, HDIM, 0, 0, 0);
    // 4) V^T = Wv x^T + bv(row)  -> split bf16   [1024 x 8192]
    dim3 gvt(MDIM / TN, HDIM / TM, 1);     // (64, 8)
    gemm_nt_bf3<<<gvt, blk, DSMEM_BYTES>>>(g_wvhi, g_wvlo, HDIM, g_xhi, g_xlo, HDIM,
        nullptr, g_vthi, g_vtlo, MDIM, bv, 2, 1.f, HDIM, 0, 0, 0);

    // 5) scores = Q K^T / 8 (per batch) -> fp32
    dim3 gsc(SDIM / TN, SDIM / TM, BDIM);  // (32, 32, 2)
    gemm_nt_bf3<<<gsc, blk, DSMEM_BYTES>>>(g_qhi, g_qlo, HDIM, g_khi, g_klo, HDIM,
        g_s, nullptr, nullptr, SDIM, nullptr, 0, 0.125f, HDIM,
        (long long)SDIM * HDIM, (long long)SDIM * HDIM, (long long)SDIM * SDIM);

    // 6) softmax -> split bf16 P
    softmax_rows<<<BDIM * SDIM, blk>>>(g_s, g_phi, g_plo);

    // 7) attn = P V (per batch): A=P [4096x4096], B=V^T [1024 x 8192] -> split bf16
    dim3 gpv(HDIM / TN, SDIM / TM, BDIM);  // (8, 32, 2)
    gemm_nt_bf3<<<gpv, blk, DSMEM_BYTES>>>(g_phi, g_plo, SDIM, g_vthi, g_vtlo, MDIM,
        nullptr, g_athi, g_atlo, HDIM, nullptr, 0, 1.f, SDIM,
        (long long)SDIM * SDIM, (long long)SDIM, (long long)SDIM * HDIM);

    // 8) out = attn Wo^T + bo -> fp32
    gemm_nt_bf3<<<gproj, blk, DSMEM_BYTES>>>(g_athi, g_atlo, HDIM, g_wohi, g_wolo, HDIM,
        out, nullptr, nullptr, HDIM, bo, 1, 1.f, HDIM, 0, 0, 0);
}